// round 1
// baseline (speedup 1.0000x reference)
#include <cuda_runtime.h>

#define NOISE   128
#define OUTF    512
#define XCOLS   640        // 128 noise + 512 feats
#define WCOLS   262656     // 512*512 + 512
#define WB_OFF  262144

#define KB          16
#define CHUNKS_TOTAL 4137  // 4096 (main) + 32 (feat-bias) + 8 (noise-bias) + 1 (const bias)
#define SPLITS      18
#define CH_PER      ((CHUNKS_TOTAL + SPLITS - 1) / SPLITS)   // 230

#define MB 128
#define NB 64
#define AS_STRIDE 130      // 128 + 2 pad: conflict-free STS/LDS, keeps 8B alignment

__device__ __forceinline__ void fma2(unsigned long long& d, unsigned long long a, unsigned long long b) {
    asm("fma.rn.f32x2 %0, %1, %2, %3;" : "=l"(d) : "l"(a), "l"(b), "l"(d));
}
__device__ __forceinline__ unsigned long long pack2(float x) {
    unsigned long long r;
    asm("mov.b64 %0, {%1, %1};" : "=l"(r) : "f"(x));
    return r;
}
__device__ __forceinline__ void unpack2(unsigned long long v, float& lo, float& hi) {
    asm("mov.b64 {%0, %1}, %2;" : "=f"(lo), "=f"(hi) : "l"(v));
}

__global__ void zero_out_kernel(float* out) {
    int i = blockIdx.x * blockDim.x + threadIdx.x;
    float4 z = make_float4(0.f, 0.f, 0.f, 0.f);
    reinterpret_cast<float4*>(out)[i] = z;
}

__global__ __launch_bounds__(256, 2)
void hyper_main(const float* __restrict__ x, const float* __restrict__ W,
                const float* __restrict__ bv, float* __restrict__ out)
{
    __shared__ float As[2][KB][AS_STRIDE];
    __shared__ float Bs[2][KB][NB];

    const int m0 = blockIdx.x * MB;          // batch tile (2 tiles)
    const int n0 = blockIdx.y * NB;          // output tile (8 tiles)
    const int s  = blockIdx.z;               // K-split
    const int c0 = s * CH_PER;
    const int c1 = min(CHUNKS_TOTAL, c0 + CH_PER);

    const int tid = threadIdx.x;
    // A-staging role: thread -> (local batch, half of the 16 kk's)
    const int sb = tid >> 1;                 // 0..127
    const int sp = tid & 1;                  // 0..1
    // B-staging role: thread -> (kk row, float4 within 64-wide row)
    const int skk = tid >> 4;                // 0..15
    const int sf  = tid & 15;                // 0..15
    // compute role
    const int tx = tid & 15;                 // o-group: o = n0 + tx*4 + q
    const int ty = tid >> 4;                 // b-group: b = m0 + ty*8 + ...

    const float* xr = x + (long)(m0 + sb) * XCOLS;

    unsigned long long acc[4][4];
    #pragma unroll
    for (int i = 0; i < 4; i++)
        #pragma unroll
        for (int j = 0; j < 4; j++) acc[i][j] = 0ull;

    // ---- prefetch registers (live across compute to overlap LDG latency) ----
    float4 fa0, fa1, fb;
    float  nv = 0.f;
    int    caseid = 0;

    auto prefetch = [&](int c) {
        if (c < 4096) {                      // main term: noise[b,k]*feats[b,i] * W[k, i*512+o]
            caseid = 0;
            int k  = c >> 5;
            int i0 = (c & 31) << 4;
            nv  = xr[k];
            fa0 = *reinterpret_cast<const float4*>(xr + NOISE + i0 + sp * 8);
            fa1 = *reinterpret_cast<const float4*>(xr + NOISE + i0 + sp * 8 + 4);
            const float* wp = W + (long)k * WCOLS + (long)(i0 + skk) * OUTF + n0;
            fb = *reinterpret_cast<const float4*>(wp + sf * 4);
        } else if (c < 4128) {               // feats @ bias-weight
            caseid = 1;
            int i0 = (c - 4096) << 4;
            fa0 = *reinterpret_cast<const float4*>(xr + NOISE + i0 + sp * 8);
            fa1 = *reinterpret_cast<const float4*>(xr + NOISE + i0 + sp * 8 + 4);
            const float* bp = bv + (long)(i0 + skk) * OUTF + n0;
            fb = *reinterpret_cast<const float4*>(bp + sf * 4);
        } else if (c < 4136) {               // noise @ W_bias
            caseid = 2;
            int k0 = (c - 4128) << 4;
            fa0 = *reinterpret_cast<const float4*>(xr + k0 + sp * 8);
            fa1 = *reinterpret_cast<const float4*>(xr + k0 + sp * 8 + 4);
            const float* wp = W + (long)(k0 + skk) * WCOLS + WB_OFF + n0;
            fb = *reinterpret_cast<const float4*>(wp + sf * 4);
        } else {                             // constant bias row (A = 1 for kk==0 only)
            caseid = 3;
            const float* bp = bv + WB_OFF + n0;
            fb = *reinterpret_cast<const float4*>(bp + sf * 4);
        }
    };

    auto store_stage = [&](int buf) {
        float a[8];
        if (caseid == 0) {
            a[0] = nv * fa0.x; a[1] = nv * fa0.y; a[2] = nv * fa0.z; a[3] = nv * fa0.w;
            a[4] = nv * fa1.x; a[5] = nv * fa1.y; a[6] = nv * fa1.z; a[7] = nv * fa1.w;
        } else if (caseid == 3) {
            #pragma unroll
            for (int j = 0; j < 8; j++) a[j] = 0.f;
            if (sp == 0) a[0] = 1.f;
        } else {
            a[0] = fa0.x; a[1] = fa0.y; a[2] = fa0.z; a[3] = fa0.w;
            a[4] = fa1.x; a[5] = fa1.y; a[6] = fa1.z; a[7] = fa1.w;
        }
        #pragma unroll
        for (int j = 0; j < 8; j++) As[buf][sp * 8 + j][sb] = a[j];
        *reinterpret_cast<float4*>(&Bs[buf][skk][sf * 4]) = fb;
    };

    auto compute = [&](int buf) {
        #pragma unroll
        for (int kk = 0; kk < KB; kk++) {
            const unsigned long long* ap =
                reinterpret_cast<const unsigned long long*>(&As[buf][kk][ty * 8]);
            unsigned long long a2[4];
            #pragma unroll
            for (int bp = 0; bp < 4; bp++) a2[bp] = ap[bp];
            float4 w = *reinterpret_cast<const float4*>(&Bs[buf][kk][tx * 4]);
            unsigned long long w2[4];
            w2[0] = pack2(w.x); w2[1] = pack2(w.y); w2[2] = pack2(w.z); w2[3] = pack2(w.w);
            #pragma unroll
            for (int bp = 0; bp < 4; bp++)
                #pragma unroll
                for (int q = 0; q < 4; q++)
                    fma2(acc[bp][q], a2[bp], w2[q]);
        }
    };

    const int nCh = c1 - c0;
    prefetch(c0);
    store_stage(0);
    for (int j = 0; j < nCh; j++) {
        __syncthreads();
        const int buf = j & 1;
        if (j + 1 < nCh) prefetch(c0 + j + 1);   // LDG in flight during compute
        compute(buf);
        if (j + 1 < nCh) store_stage(buf ^ 1);   // write OTHER buffer; sync guards reuse
    }

    // ---- epilogue: merge K-splits via reduction atomics ----
    #pragma unroll
    for (int bp = 0; bp < 4; bp++) {
        int b = m0 + ty * 8 + bp * 2;
        #pragma unroll
        for (int q = 0; q < 4; q++) {
            float lo, hi;
            unpack2(acc[bp][q], lo, hi);
            int o = n0 + tx * 4 + q;
            atomicAdd(&out[(long)b * OUTF + o], lo);
            atomicAdd(&out[(long)(b + 1) * OUTF + o], hi);
        }
    }
}

extern "C" void kernel_launch(void* const* d_in, const int* in_sizes, int n_in,
                              void* d_out, int out_size) {
    const float* x  = (const float*)d_in[0];   // (256, 640)
    const float* W  = (const float*)d_in[1];   // (128, 262656)
    const float* bv = (const float*)d_in[2];   // (262656,)
    float* out = (float*)d_out;                // (256, 512)

    zero_out_kernel<<<128, 256>>>(out);        // 32768 float4 = 131072 floats
    dim3 grid(2, 8, SPLITS);
    hyper_main<<<grid, 256>>>(x, W, bv, out);
}